// round 14
// baseline (speedup 1.0000x reference)
#include <cuda_runtime.h>
#include <cuda_bf16.h>
#include <cstdint>

// ---------------- problem constants ----------------
#define NN       2304
#define KDIM     128
#define KP       64              // packed bf16-pair count along K
#define NCOLS    14400
#define E0W      1060
#define EY_ELEMS (NN * NCOLS)    // 33177600
#define E0_ELEMS 1123600

// GEMM tiling
#define GM 256                   // rows per CTA (2 row-tiles of 16 per warp)
#define GN 64                    // cols per CTA (8 column tiles of 8)
#define NMG (NN / 16)            // 144 row fragment groups
#define FRAG_N (NMG * 8 * 32)    // A fragments per plane = 36864
#define NCT (NCOLS / 8)          // 1800 column tiles
#define FRAGB_N (NCT * 8 * 32)   // B fragments = 460800

// ---------------- scratch (device globals, allocation-free) ----------------
__device__ float    g_eta[NN];
__device__ uint32_t g_hhi[NN * KP];
__device__ uint32_t g_hlo[NN * KP];
__device__ __align__(16) uint4 g_fragHi[FRAG_N];   // A fragments (hi plane)
__device__ __align__(16) uint4 g_fragLo[FRAG_N];   // A fragments (lo plane)
__device__ __align__(16) uint4 g_Bfrag[FRAGB_N];   // B fragments (bh0,bh1,bl0,bl1)
__device__ __align__(16) int g_tbl[NCOLS];         // packed (tij<<9 | ab)
__device__ __align__(16) float g_Ey[EY_ELEMS];     // fallback output modes only
__device__ float    g_Tre[NN];
__device__ float    g_Tim[NN];
__device__ float    g_zero[2 * E0_ELEMS];          // universal null fallback

// ---------------------------------------------------------------------------
// helpers
// ---------------------------------------------------------------------------
__device__ __forceinline__ void bf16_split_pack(float x0, float x1,
                                                uint32_t& hi, uint32_t& lo)
{
    __nv_bfloat16 h0 = __float2bfloat16_rn(x0);
    __nv_bfloat16 h1 = __float2bfloat16_rn(x1);
    hi = (uint32_t)__bfloat16_as_ushort(h0)
       | ((uint32_t)__bfloat16_as_ushort(h1) << 16);
    __nv_bfloat16 l0 = __float2bfloat16_rn(x0 - __bfloat162float(h0));
    __nv_bfloat16 l1 = __float2bfloat16_rn(x1 - __bfloat162float(h1));
    lo = (uint32_t)__bfloat16_as_ushort(l0)
       | ((uint32_t)__bfloat16_as_ushort(l1) << 16);
}

// D += A(16x16 bf16) * B(16x8 bf16), fp32 accum. sm_80+ HMMA.
__device__ __forceinline__ void mma_bf16(float* c, const uint4& a,
                                         uint32_t b0, uint32_t b1)
{
    asm volatile(
        "mma.sync.aligned.m16n8k16.row.col.f32.bf16.bf16.f32 "
        "{%0,%1,%2,%3}, {%4,%5,%6,%7}, {%8,%9}, {%0,%1,%2,%3};\n"
        : "+f"(c[0]), "+f"(c[1]), "+f"(c[2]), "+f"(c[3])
        : "r"(a.x), "r"(a.y), "r"(a.z), "r"(a.w), "r"(b0), "r"(b1));
}

// ---------------------------------------------------------------------------
// Kernel 1: the two small MLPs; also emits split-bf16 packed h.
// ---------------------------------------------------------------------------
__global__ void __launch_bounds__(128) mlp_kernel(
    const float* hs,
    const float* nW0, const float* nb0, const float* nW1, const float* nb1,
    const float* nW2, const float* nb2,
    const float* eW0, const float* eb0, const float* eW1, const float* eb1)
{
    const float* HS  = hs  ? hs  : g_zero;
    const float* NW0 = nW0 ? nW0 : g_zero;  const float* NB0 = nb0 ? nb0 : g_zero;
    const float* NW1 = nW1 ? nW1 : g_zero;  const float* NB1 = nb1 ? nb1 : g_zero;
    const float* NW2 = nW2 ? nW2 : g_zero;  const float* NB2 = nb2 ? nb2 : g_zero;
    const float* EW0 = eW0 ? eW0 : g_zero;  const float* EB0 = eb0 ? eb0 : g_zero;
    const float* EW1 = eW1 ? eW1 : g_zero;  const float* EB1 = eb1 ? eb1 : g_zero;

    int p = blockIdx.x, j = threadIdx.x;
    float x = HS[p];
    __shared__ float s1[KDIM], s2[KDIM];

    // ---- neff branch ----
    s1[j] = fmaxf(fmaf(x, NW0[j], NB0[j]), 0.0f);
    __syncthreads();
    float acc = NB1[j];
#pragma unroll 8
    for (int k = 0; k < KDIM; ++k) acc = fmaf(s1[k], NW1[k * KDIM + j], acc);
    float h2 = fmaxf(acc, 0.0f);
    __syncthreads();
    s2[j] = h2 * NW2[j];
    __syncthreads();
    for (int off = 64; off > 0; off >>= 1) {
        if (j < off) s2[j] += s2[j + off];
        __syncthreads();
    }
    if (j == 0) {
        float neff = s2[0] + NB2[0];
        g_eta[p] = neff / (neff + 1.0f);   // N0 = 1
    }
    __syncthreads();

    // ---- enn branch ----
    s1[j] = fmaxf(fmaf(x, EW0[j], EB0[j]), 0.0f);
    __syncthreads();
    acc = EB1[j];
#pragma unroll 8
    for (int k = 0; k < KDIM; ++k) acc = fmaf(s1[k], EW1[k * KDIM + j], acc);
    float hval = fmaxf(acc, 0.0f);
    __syncthreads();
    s2[j] = hval;
    __syncthreads();
    if (j < KP) {
        uint32_t hi, lo;
        bf16_split_pack(s2[2 * j], s2[2 * j + 1], hi, lo);
        g_hhi[p * KP + j] = hi;
        g_hlo[p * KP + j] = lo;
    }
}

// ---------------------------------------------------------------------------
// Kernel 1b: pack eW2 directly into B-FRAGMENT order (+ esum table).
// One thread per (ct, ks, lane): uint4 = (bh0, bh1, bl0, bl1), exactly the
// two B fragment registers (hi/lo planes) lane needs for mma step ks,
// column tile ct. Values bit-identical to the smem path of rounds 6-13.
// ---------------------------------------------------------------------------
__global__ void __launch_bounds__(256) wfrag_kernel(const float* W_in)
{
    const float* W = W_in ? W_in : g_zero;
    int id = blockIdx.x * 256 + threadIdx.x;          // over FRAGB_N

    // piggyback: esum gather table (first NCOLS threads)
    if (id < NCOLS) {
        int e = id;
        int y = e / 120, x = e - y * 120;
        int i = y / 20, a = y - i * 20;
        int j = x / 20, b = x - j * 20;
        int tij = (i * 20) * E0W + j * 20;
        g_tbl[e] = (tij << 9) | (a * 20 + b);
    }

    if (id >= FRAGB_N) return;
    int lane = id & 31;
    int ks   = (id >> 5) & 7;
    int ct   = id >> 8;
    int qrow = lane >> 2, qk = lane & 3;
    int col  = ct * 8 + qrow;
    int kp0  = ks * 8 + qk;      // b0: k-pairs kb+qk
    int kp1  = kp0 + 4;          // b1: k-pairs kb+qk+4

    float x0 = W[(2 * kp0)     * NCOLS + col];
    float x1 = W[(2 * kp0 + 1) * NCOLS + col];
    float y0 = W[(2 * kp1)     * NCOLS + col];
    float y1 = W[(2 * kp1 + 1) * NCOLS + col];

    uint4 v;
    bf16_split_pack(x0, x1, v.x, v.z);   // bh0, bl0
    bf16_split_pack(y0, y1, v.y, v.w);   // bh1, bl1
    g_Bfrag[id] = v;
}

// ---------------------------------------------------------------------------
// Kernel 1c: swizzle h into A-fragment order (round-8 proven grid-stride).
// ---------------------------------------------------------------------------
__global__ void __launch_bounds__(256) hfrag_kernel()
{
    int id = blockIdx.x * 256 + threadIdx.x;
    if (id >= 2 * FRAG_N) return;
    int plane = id / FRAG_N;
    int r = id - plane * FRAG_N;
    int lane = r & 31;
    int ks = (r >> 5) & 7;
    int mg = r >> 8;
    int qrow = lane >> 2, qk = lane & 3;
    int row = mg * 16 + qrow;
    int kp  = ks * 8 + qk;
    const uint32_t* src = plane ? g_hlo : g_hhi;
    uint4 v;
    v.x = src[row * KP + kp];
    v.y = src[(row + 8) * KP + kp];
    v.z = src[row * KP + kp + 4];
    v.w = src[(row + 8) * KP + kp + 4];
    (plane ? g_fragLo : g_fragHi)[r] = v;
}

// ---------------------------------------------------------------------------
// Kernel 2: HMMA bf16 split GEMM — SMEM-FREE. All operands arrive as
// coalesced LDG.128 fragments (A from g_fragHi/Lo, B from g_Bfrag).
// No staging prologue, no __syncthreads, no LDS in the loop.
// Accumulation order per output identical to rounds 8/13.
// ---------------------------------------------------------------------------
__global__ void __launch_bounds__(256) gemm_mma(
    const float* bias_in, float* eyout)
{
    const float* bias = bias_in ? bias_in : g_zero;
    float* o = eyout ? eyout : g_Ey;

    const int c0  = blockIdx.x * GN;
    const int ct0 = blockIdx.x * 8;      // first column tile
    const int p0  = blockIdx.y * GM;
    const int t = threadIdx.x;
    const int w = t >> 5, lane = t & 31;

    const int r0   = p0 + w * 32;
    const int qrow = lane >> 2;
    const int qk   = lane & 3;
    const int mg0  = r0 >> 4;

    float acc[2][8][4];
#pragma unroll
    for (int u = 0; u < 2; ++u)
#pragma unroll
        for (int s = 0; s < 8; ++s)
#pragma unroll
            for (int q = 0; q < 4; ++q) acc[u][s][q] = 0.0f;

    for (int ks = 0; ks < 8; ++ks) {
        uint4 ah0 = g_fragHi[(mg0 * 8 + ks) * 32 + lane];
        uint4 al0 = g_fragLo[(mg0 * 8 + ks) * 32 + lane];
        uint4 ah1 = g_fragHi[((mg0 + 1) * 8 + ks) * 32 + lane];
        uint4 al1 = g_fragLo[((mg0 + 1) * 8 + ks) * 32 + lane];

#pragma unroll
        for (int s = 0; s < 8; ++s) {
            uint4 b = g_Bfrag[((ct0 + s) * 8 + ks) * 32 + lane];
            mma_bf16(acc[0][s], ah0, b.x, b.y);   // hi·hi
            mma_bf16(acc[0][s], ah0, b.z, b.w);   // hi·lo
            mma_bf16(acc[0][s], al0, b.x, b.y);   // lo·hi
            mma_bf16(acc[1][s], ah1, b.x, b.y);
            mma_bf16(acc[1][s], ah1, b.z, b.w);
            mma_bf16(acc[1][s], al1, b.x, b.y);
        }
    }

    // epilogue: bias + direct coalesced float2 stores (two row tiles)
#pragma unroll
    for (int s = 0; s < 8; ++s) {
        int c = c0 + s * 8 + qk * 2;
        float b0 = bias[c], b1 = bias[c + 1];
#pragma unroll
        for (int u = 0; u < 2; ++u) {
            size_t r = (size_t)(r0 + 16 * u + qrow);
            float2 v0 = make_float2(acc[u][s][0] + b0, acc[u][s][1] + b1);
            float2 v1 = make_float2(acc[u][s][2] + b0, acc[u][s][3] + b1);
            *(float2*)&o[r * NCOLS + c]       = v0;
            *(float2*)&o[(r + 8) * NCOLS + c] = v1;
        }
    }
}

// ---------------------------------------------------------------------------
// Kernel 3: T[p] = 0.005 * eta[p] * sum_e Ey[p,e] * E0_slice[p,e]
// float4 Ey + int4 table, separate E0r/E0i gathers (round-13 proven).
// ---------------------------------------------------------------------------
__global__ void __launch_bounds__(256) esum_kernel(
    const float* ey_in, const float* E0r_in, const float* E0i_in,
    int stride, float* outT)
{
    const float* ey  = ey_in  ? ey_in  : g_Ey;
    const float* E0r = E0r_in ? E0r_in : g_zero;
    const float* E0i = E0i_in ? E0i_in : g_zero;

    const int p = blockIdx.x, t = threadIdx.x;
    const int f0  = p * 400;
    const int r0p = f0 / 960;
    const int c0p = f0 - r0p * 960;
    const int base = r0p * E0W + c0p;
    const int lim  = 960 - c0p;

    float sre = 0.f, sim = 0.f;
    const float4* ey4  = (const float4*)(ey + (size_t)p * NCOLS);
    const int4*   tbl4 = (const int4*)g_tbl;

    for (int q = t; q < NCOLS / 4; q += 256) {
        int4   tb = tbl4[q];
        float4 g  = ey4[q];

        int ab0 = tb.x & 511;
        int i0  = base + (tb.x >> 9) + ab0 + ((ab0 >= lim) ? 100 : 0);
        int ab1 = tb.y & 511;
        int i1  = base + (tb.y >> 9) + ab1 + ((ab1 >= lim) ? 100 : 0);
        int ab2 = tb.z & 511;
        int i2  = base + (tb.z >> 9) + ab2 + ((ab2 >= lim) ? 100 : 0);
        int ab3 = tb.w & 511;
        int i3  = base + (tb.w >> 9) + ab3 + ((ab3 >= lim) ? 100 : 0);

        sre = fmaf(g.x, E0r[i0 * stride], sre);
        sim = fmaf(g.x, E0i[i0 * stride], sim);
        sre = fmaf(g.y, E0r[i1 * stride], sre);
        sim = fmaf(g.y, E0i[i1 * stride], sim);
        sre = fmaf(g.z, E0r[i2 * stride], sre);
        sim = fmaf(g.z, E0i[i2 * stride], sim);
        sre = fmaf(g.w, E0r[i3 * stride], sre);
        sim = fmaf(g.w, E0i[i3 * stride], sim);
    }

#pragma unroll
    for (int off = 16; off > 0; off >>= 1) {
        sre += __shfl_down_sync(0xffffffffu, sre, off);
        sim += __shfl_down_sync(0xffffffffu, sim, off);
    }
    __shared__ float wr[8], wi[8];
    if ((t & 31) == 0) { wr[t >> 5] = sre; wi[t >> 5] = sim; }
    __syncthreads();
    if (t == 0) {
        float tre = 0.f, tim = 0.f;
        for (int q = 0; q < 8; ++q) { tre += wr[q]; tim += wi[q]; }
        float s = 0.005f * g_eta[p];
        g_Tre[p] = s * tre;
        g_Tim[p] = s * tim;
        if (outT) outT[p] = s * tre;
    }
}

// ---------------------------------------------------------------------------
// Kernel 4 (fallback modes only): scalar-float pack, never exceeds cnt.
// ---------------------------------------------------------------------------
__global__ void pack_kernel(float* out, long long cnt, int mode)
{
    long long i = (long long)blockIdx.x * 256 + threadIdx.x;
    if (i >= cnt) return;
    float v = 0.f;
    if (mode == 1 || mode == 5) {
        if (i < EY_ELEMS) v = g_Ey[i];
        else {
            long long q = i - EY_ELEMS;
            if (q < 2 * NN) v = (q & 1) ? g_Tim[q >> 1] : g_Tre[q >> 1];
        }
    } else if (mode == 2) v = g_Ey[i];
    else if (mode == 3) v = (i & 1) ? g_Tim[i >> 1] : g_Tre[i >> 1];
    else if (mode == 4) v = g_Tre[i];
    out[i] = v;
}

// ---------------------------------------------------------------------------
extern "C" void kernel_launch(void* const* d_in, const int* in_sizes, int n_in,
                              void* d_out, int out_size)
{
    if (n_in > 64) n_in = 64;
    bool used[64];
    for (int i = 0; i < 64; ++i) used[i] = false;
    auto take = [&](int sz) -> const float* {
        for (int i = 0; i < n_in; ++i)
            if (!used[i] && in_sizes[i] == sz) {
                used[i] = true;
                return (const float*)d_in[i];
            }
        return nullptr;
    };

    const float* hs = take(2304);
    const float* E0r; const float* E0i; int e0stride;
    {
        const float* a = take(E0_ELEMS);
        if (a) { E0r = a; E0i = take(E0_ELEMS); e0stride = 1; }
        else {
            const float* c1 = take(2 * E0_ELEMS);
            const float* c2 = take(2 * E0_ELEMS);
            if (c1 && c2)      { E0r = c1; E0i = c2;     e0stride = 2; }
            else if (c1)       { E0r = c1; E0i = c1 + 1; e0stride = 2; }
            else               { E0r = nullptr; E0i = nullptr; e0stride = 1; }
        }
    }
    const float* nW0 = take(128);
    const float* nb0 = take(128);
    const float* nW1 = take(16384);
    const float* nb1 = take(128);
    const float* nW2 = take(128);
    const float* nb2 = take(1);
    const float* eW0 = take(128);
    const float* eb0 = take(128);
    const float* eW1 = take(16384);
    const float* eb1 = take(128);
    const float* eW2 = take(1843200);
    const float* eb2 = take(14400);
    float* out = (float*)d_out;

    const bool fast = (out_size == EY_ELEMS + NN);

    mlp_kernel<<<NN, 128>>>(hs, nW0, nb0, nW1, nb1, nW2, nb2,
                            eW0, eb0, eW1, eb1);
    wfrag_kernel<<<(FRAGB_N + 255) / 256, 256>>>(eW2);  // + esum table
    hfrag_kernel<<<(2 * FRAG_N + 255) / 256, 256>>>();

    gemm_mma<<<dim3(NCOLS / GN, NN / GM), 256>>>(eb2, fast ? out : nullptr);

    esum_kernel<<<NN, 256>>>(fast ? out : nullptr, E0r, E0i, e0stride,
                             fast ? out + EY_ELEMS : nullptr);

    if (!fast) {
        long long cnt; int mode;
        if      (out_size == EY_ELEMS + 2 * NN) { mode = 1; cnt = out_size; }
        else if (out_size == EY_ELEMS)          { mode = 2; cnt = out_size; }
        else if (out_size == 2 * NN)            { mode = 3; cnt = out_size; }
        else if (out_size == NN)                { mode = 4; cnt = out_size; }
        else { mode = 5; cnt = out_size / 4; }
        if (cnt < 1) cnt = 1;
        pack_kernel<<<(unsigned)((cnt + 255) / 256), 256>>>(out, cnt, mode);
    }
}

// round 15
// speedup vs baseline: 1.0077x; 1.0077x over previous
#include <cuda_runtime.h>
#include <cuda_bf16.h>
#include <cstdint>

// ---------------- problem constants ----------------
#define NN       2304
#define KDIM     128
#define KP       64              // packed bf16-pair count along K
#define NCOLS    14400
#define E0W      1060
#define EY_ELEMS (NN * NCOLS)    // 33177600
#define E0_ELEMS 1123600

// GEMM tiling (round-13 champion shape)
#define GM 256                   // rows per CTA (2 row-tiles of 16 per warp)
#define GN 64                    // cols per CTA (8 column tiles of 8)
#define NMG (NN / 16)            // 144 row fragment groups
#define FRAG_N (NMG * 8 * 32)    // A fragments per plane = 36864
#define NCT (NCOLS / 8)          // 1800 column tiles
#define FRAGB_N (NCT * 8 * 32)   // B fragments = 460800

// ---------------- scratch (device globals, allocation-free) ----------------
__device__ float    g_eta[NN];
__device__ uint32_t g_hhi[NN * KP];
__device__ uint32_t g_hlo[NN * KP];
__device__ __align__(16) uint4 g_fragHi[FRAG_N];   // A fragments (hi plane)
__device__ __align__(16) uint4 g_fragLo[FRAG_N];   // A fragments (lo plane)
__device__ __align__(16) uint4 g_Bfrag[FRAGB_N];   // B fragments (bh0,bh1,bl0,bl1)
__device__ __align__(16) int g_tbl[NCOLS];         // packed (tij<<9 | ab)
__device__ __align__(16) float g_Ey[EY_ELEMS];     // fallback output modes only
__device__ float    g_Tre[NN];
__device__ float    g_Tim[NN];
__device__ float    g_zero[2 * E0_ELEMS];          // universal null fallback

// ---------------------------------------------------------------------------
// helpers
// ---------------------------------------------------------------------------
__device__ __forceinline__ void bf16_split_pack(float x0, float x1,
                                                uint32_t& hi, uint32_t& lo)
{
    __nv_bfloat16 h0 = __float2bfloat16_rn(x0);
    __nv_bfloat16 h1 = __float2bfloat16_rn(x1);
    hi = (uint32_t)__bfloat16_as_ushort(h0)
       | ((uint32_t)__bfloat16_as_ushort(h1) << 16);
    __nv_bfloat16 l0 = __float2bfloat16_rn(x0 - __bfloat162float(h0));
    __nv_bfloat16 l1 = __float2bfloat16_rn(x1 - __bfloat162float(h1));
    lo = (uint32_t)__bfloat16_as_ushort(l0)
       | ((uint32_t)__bfloat16_as_ushort(l1) << 16);
}

// D += A(16x16 bf16) * B(16x8 bf16), fp32 accum. sm_80+ HMMA.
__device__ __forceinline__ void mma_bf16(float* c, const uint4& a,
                                         uint32_t b0, uint32_t b1)
{
    asm volatile(
        "mma.sync.aligned.m16n8k16.row.col.f32.bf16.bf16.f32 "
        "{%0,%1,%2,%3}, {%4,%5,%6,%7}, {%8,%9}, {%0,%1,%2,%3};\n"
        : "+f"(c[0]), "+f"(c[1]), "+f"(c[2]), "+f"(c[3])
        : "r"(a.x), "r"(a.y), "r"(a.z), "r"(a.w), "r"(b0), "r"(b1));
}

// ---------------------------------------------------------------------------
// Kernel 1: the two small MLPs; also emits split-bf16 packed h.
// ---------------------------------------------------------------------------
__global__ void __launch_bounds__(128) mlp_kernel(
    const float* hs,
    const float* nW0, const float* nb0, const float* nW1, const float* nb1,
    const float* nW2, const float* nb2,
    const float* eW0, const float* eb0, const float* eW1, const float* eb1)
{
    const float* HS  = hs  ? hs  : g_zero;
    const float* NW0 = nW0 ? nW0 : g_zero;  const float* NB0 = nb0 ? nb0 : g_zero;
    const float* NW1 = nW1 ? nW1 : g_zero;  const float* NB1 = nb1 ? nb1 : g_zero;
    const float* NW2 = nW2 ? nW2 : g_zero;  const float* NB2 = nb2 ? nb2 : g_zero;
    const float* EW0 = eW0 ? eW0 : g_zero;  const float* EB0 = eb0 ? eb0 : g_zero;
    const float* EW1 = eW1 ? eW1 : g_zero;  const float* EB1 = eb1 ? eb1 : g_zero;

    int p = blockIdx.x, j = threadIdx.x;
    float x = HS[p];
    __shared__ float s1[KDIM], s2[KDIM];

    // ---- neff branch ----
    s1[j] = fmaxf(fmaf(x, NW0[j], NB0[j]), 0.0f);
    __syncthreads();
    float acc = NB1[j];
#pragma unroll 8
    for (int k = 0; k < KDIM; ++k) acc = fmaf(s1[k], NW1[k * KDIM + j], acc);
    float h2 = fmaxf(acc, 0.0f);
    __syncthreads();
    s2[j] = h2 * NW2[j];
    __syncthreads();
    for (int off = 64; off > 0; off >>= 1) {
        if (j < off) s2[j] += s2[j + off];
        __syncthreads();
    }
    if (j == 0) {
        float neff = s2[0] + NB2[0];
        g_eta[p] = neff / (neff + 1.0f);   // N0 = 1
    }
    __syncthreads();

    // ---- enn branch ----
    s1[j] = fmaxf(fmaf(x, EW0[j], EB0[j]), 0.0f);
    __syncthreads();
    acc = EB1[j];
#pragma unroll 8
    for (int k = 0; k < KDIM; ++k) acc = fmaf(s1[k], EW1[k * KDIM + j], acc);
    float hval = fmaxf(acc, 0.0f);
    __syncthreads();
    s2[j] = hval;
    __syncthreads();
    if (j < KP) {
        uint32_t hi, lo;
        bf16_split_pack(s2[2 * j], s2[2 * j + 1], hi, lo);
        g_hhi[p * KP + j] = hi;
        g_hlo[p * KP + j] = lo;
    }
}

// ---------------------------------------------------------------------------
// Kernel 1b: pack eW2 into B-FRAGMENT order (+ esum table). Round-14 proven
// (values bit-identical to the smem path of rounds 6-13).
// ---------------------------------------------------------------------------
__global__ void __launch_bounds__(256) wfrag_kernel(const float* W_in)
{
    const float* W = W_in ? W_in : g_zero;
    int id = blockIdx.x * 256 + threadIdx.x;          // over FRAGB_N

    // piggyback: esum gather table (first NCOLS threads)
    if (id < NCOLS) {
        int e = id;
        int y = e / 120, x = e - y * 120;
        int i = y / 20, a = y - i * 20;
        int j = x / 20, b = x - j * 20;
        int tij = (i * 20) * E0W + j * 20;
        g_tbl[e] = (tij << 9) | (a * 20 + b);
    }

    if (id >= FRAGB_N) return;
    int lane = id & 31;
    int ks   = (id >> 5) & 7;
    int ct   = id >> 8;
    int qrow = lane >> 2, qk = lane & 3;
    int col  = ct * 8 + qrow;
    int kp0  = ks * 8 + qk;      // b0: k-pairs kb+qk
    int kp1  = kp0 + 4;          // b1: k-pairs kb+qk+4

    float x0 = W[(2 * kp0)     * NCOLS + col];
    float x1 = W[(2 * kp0 + 1) * NCOLS + col];
    float y0 = W[(2 * kp1)     * NCOLS + col];
    float y1 = W[(2 * kp1 + 1) * NCOLS + col];

    uint4 v;
    bf16_split_pack(x0, x1, v.x, v.z);   // bh0, bl0
    bf16_split_pack(y0, y1, v.y, v.w);   // bh1, bl1
    g_Bfrag[id] = v;
}

// ---------------------------------------------------------------------------
// Kernel 1c: swizzle h into A-fragment order (round-8 proven grid-stride).
// ---------------------------------------------------------------------------
__global__ void __launch_bounds__(256) hfrag_kernel()
{
    int id = blockIdx.x * 256 + threadIdx.x;
    if (id >= 2 * FRAG_N) return;
    int plane = id / FRAG_N;
    int r = id - plane * FRAG_N;
    int lane = r & 31;
    int ks = (r >> 5) & 7;
    int mg = r >> 8;
    int qrow = lane >> 2, qk = lane & 3;
    int row = mg * 16 + qrow;
    int kp  = ks * 8 + qk;
    const uint32_t* src = plane ? g_hlo : g_hhi;
    uint4 v;
    v.x = src[row * KP + kp];
    v.y = src[(row + 8) * KP + kp];
    v.z = src[row * KP + kp + 4];
    v.w = src[(row + 8) * KP + kp + 4];
    (plane ? g_fragLo : g_fragHi)[r] = v;
}

// ---------------------------------------------------------------------------
// Kernel 2: HMMA bf16 split GEMM. Round-13 shape (GM=256, smem B tile with
// 18x reuse) + round-14 fragment format in smem: stage is a contiguous 32KB
// copy of g_Bfrag; inner loop does ONE LDS.128 per (s,ks) instead of 4
// scalar LDS.32 (4x fewer LDS instructions, conflict-free phases).
// Accumulation order per output identical to rounds 8/13.
// ---------------------------------------------------------------------------
__global__ void __launch_bounds__(256) gemm_mma(
    const float* bias_in, float* eyout)
{
    const float* bias = bias_in ? bias_in : g_zero;
    float* o = eyout ? eyout : g_Ey;

    __shared__ __align__(16) uint4 sB[2048];   // 8 ct x 8 ks x 32 lanes = 32KB

    const int c0  = blockIdx.x * GN;
    const int ct0 = blockIdx.x * 8;
    const int p0  = blockIdx.y * GM;
    const int t = threadIdx.x;
    const int w = t >> 5, lane = t & 31;

    // stage B fragments: pure contiguous copy (fully coalesced LDG.128)
    {
        const uint4* src = g_Bfrag + ct0 * 256;
#pragma unroll
        for (int i = 0; i < 8; ++i)
            sB[i * 256 + t] = src[i * 256 + t];
    }
    __syncthreads();

    const int r0   = p0 + w * 32;
    const int qrow = lane >> 2;
    const int qk   = lane & 3;
    const int mg0  = r0 >> 4;

    float acc[2][8][4];
#pragma unroll
    for (int u = 0; u < 2; ++u)
#pragma unroll
        for (int s = 0; s < 8; ++s)
#pragma unroll
            for (int q = 0; q < 4; ++q) acc[u][s][q] = 0.0f;

    for (int ks = 0; ks < 8; ++ks) {
        uint4 ah0 = g_fragHi[(mg0 * 8 + ks) * 32 + lane];
        uint4 al0 = g_fragLo[(mg0 * 8 + ks) * 32 + lane];
        uint4 ah1 = g_fragHi[((mg0 + 1) * 8 + ks) * 32 + lane];
        uint4 al1 = g_fragLo[((mg0 + 1) * 8 + ks) * 32 + lane];

#pragma unroll
        for (int s = 0; s < 8; ++s) {
            uint4 b = sB[(s * 8 + ks) * 32 + lane];   // one LDS.128
            mma_bf16(acc[0][s], ah0, b.x, b.y);   // hi·hi
            mma_bf16(acc[0][s], ah0, b.z, b.w);   // hi·lo
            mma_bf16(acc[0][s], al0, b.x, b.y);   // lo·hi
            mma_bf16(acc[1][s], ah1, b.x, b.y);
            mma_bf16(acc[1][s], ah1, b.z, b.w);
            mma_bf16(acc[1][s], al1, b.x, b.y);
        }
    }

    // epilogue: bias + direct coalesced float2 stores (two row tiles)
#pragma unroll
    for (int s = 0; s < 8; ++s) {
        int c = c0 + s * 8 + qk * 2;
        float b0 = bias[c], b1 = bias[c + 1];
#pragma unroll
        for (int u = 0; u < 2; ++u) {
            size_t r = (size_t)(r0 + 16 * u + qrow);
            float2 v0 = make_float2(acc[u][s][0] + b0, acc[u][s][1] + b1);
            float2 v1 = make_float2(acc[u][s][2] + b0, acc[u][s][3] + b1);
            *(float2*)&o[r * NCOLS + c]       = v0;
            *(float2*)&o[(r + 8) * NCOLS + c] = v1;
        }
    }
}

// ---------------------------------------------------------------------------
// Kernel 3: T[p] = 0.005 * eta[p] * sum_e Ey[p,e] * E0_slice[p,e]
// float4 Ey + int4 table, separate E0r/E0i gathers (round-13 proven).
// ---------------------------------------------------------------------------
__global__ void __launch_bounds__(256) esum_kernel(
    const float* ey_in, const float* E0r_in, const float* E0i_in,
    int stride, float* outT)
{
    const float* ey  = ey_in  ? ey_in  : g_Ey;
    const float* E0r = E0r_in ? E0r_in : g_zero;
    const float* E0i = E0i_in ? E0i_in : g_zero;

    const int p = blockIdx.x, t = threadIdx.x;
    const int f0  = p * 400;
    const int r0p = f0 / 960;
    const int c0p = f0 - r0p * 960;
    const int base = r0p * E0W + c0p;
    const int lim  = 960 - c0p;

    float sre = 0.f, sim = 0.f;
    const float4* ey4  = (const float4*)(ey + (size_t)p * NCOLS);
    const int4*   tbl4 = (const int4*)g_tbl;

    for (int q = t; q < NCOLS / 4; q += 256) {
        int4   tb = tbl4[q];
        float4 g  = ey4[q];

        int ab0 = tb.x & 511;
        int i0  = base + (tb.x >> 9) + ab0 + ((ab0 >= lim) ? 100 : 0);
        int ab1 = tb.y & 511;
        int i1  = base + (tb.y >> 9) + ab1 + ((ab1 >= lim) ? 100 : 0);
        int ab2 = tb.z & 511;
        int i2  = base + (tb.z >> 9) + ab2 + ((ab2 >= lim) ? 100 : 0);
        int ab3 = tb.w & 511;
        int i3  = base + (tb.w >> 9) + ab3 + ((ab3 >= lim) ? 100 : 0);

        sre = fmaf(g.x, E0r[i0 * stride], sre);
        sim = fmaf(g.x, E0i[i0 * stride], sim);
        sre = fmaf(g.y, E0r[i1 * stride], sre);
        sim = fmaf(g.y, E0i[i1 * stride], sim);
        sre = fmaf(g.z, E0r[i2 * stride], sre);
        sim = fmaf(g.z, E0i[i2 * stride], sim);
        sre = fmaf(g.w, E0r[i3 * stride], sre);
        sim = fmaf(g.w, E0i[i3 * stride], sim);
    }

#pragma unroll
    for (int off = 16; off > 0; off >>= 1) {
        sre += __shfl_down_sync(0xffffffffu, sre, off);
        sim += __shfl_down_sync(0xffffffffu, sim, off);
    }
    __shared__ float wr[8], wi[8];
    if ((t & 31) == 0) { wr[t >> 5] = sre; wi[t >> 5] = sim; }
    __syncthreads();
    if (t == 0) {
        float tre = 0.f, tim = 0.f;
        for (int q = 0; q < 8; ++q) { tre += wr[q]; tim += wi[q]; }
        float s = 0.005f * g_eta[p];
        g_Tre[p] = s * tre;
        g_Tim[p] = s * tim;
        if (outT) outT[p] = s * tre;
    }
}

// ---------------------------------------------------------------------------
// Kernel 4 (fallback modes only): scalar-float pack, never exceeds cnt.
// ---------------------------------------------------------------------------
__global__ void pack_kernel(float* out, long long cnt, int mode)
{
    long long i = (long long)blockIdx.x * 256 + threadIdx.x;
    if (i >= cnt) return;
    float v = 0.f;
    if (mode == 1 || mode == 5) {
        if (i < EY_ELEMS) v = g_Ey[i];
        else {
            long long q = i - EY_ELEMS;
            if (q < 2 * NN) v = (q & 1) ? g_Tim[q >> 1] : g_Tre[q >> 1];
        }
    } else if (mode == 2) v = g_Ey[i];
    else if (mode == 3) v = (i & 1) ? g_Tim[i >> 1] : g_Tre[i >> 1];
    else if (mode == 4) v = g_Tre[i];
    out[i] = v;
}

// ---------------------------------------------------------------------------
extern "C" void kernel_launch(void* const* d_in, const int* in_sizes, int n_in,
                              void* d_out, int out_size)
{
    if (n_in > 64) n_in = 64;
    bool used[64];
    for (int i = 0; i < 64; ++i) used[i] = false;
    auto take = [&](int sz) -> const float* {
        for (int i = 0; i < n_in; ++i)
            if (!used[i] && in_sizes[i] == sz) {
                used[i] = true;
                return (const float*)d_in[i];
            }
        return nullptr;
    };

    const float* hs = take(2304);
    const float* E0r; const float* E0i; int e0stride;
    {
        const float* a = take(E0_ELEMS);
        if (a) { E0r = a; E0i = take(E0_ELEMS); e0stride = 1; }
        else {
            const float* c1 = take(2 * E0_ELEMS);
            const float* c2 = take(2 * E0_ELEMS);
            if (c1 && c2)      { E0r = c1; E0i = c2;     e0stride = 2; }
            else if (c1)       { E0r = c1; E0i = c1 + 1; e0stride = 2; }
            else               { E0r = nullptr; E0i = nullptr; e0stride = 1; }
        }
    }
    const float* nW0 = take(128);
    const float* nb0 = take(128);
    const float* nW1 = take(16384);
    const float* nb1 = take(128);
    const float* nW2 = take(128);
    const float* nb2 = take(1);
    const float* eW0 = take(128);
    const float* eb0 = take(128);
    const float* eW1 = take(16384);
    const float* eb1 = take(128);
    const float* eW2 = take(1843200);
    const float* eb2 = take(14400);
    float* out = (float*)d_out;

    const bool fast = (out_size == EY_ELEMS + NN);

    mlp_kernel<<<NN, 128>>>(hs, nW0, nb0, nW1, nb1, nW2, nb2,
                            eW0, eb0, eW1, eb1);
    wfrag_kernel<<<(FRAGB_N + 255) / 256, 256>>>(eW2);  // + esum table
    hfrag_kernel<<<(2 * FRAG_N + 255) / 256, 256>>>();

    gemm_mma<<<dim3(NCOLS / GN, NN / GM), 256>>>(eb2, fast ? out : nullptr);

    esum_kernel<<<NN, 256>>>(fast ? out : nullptr, E0r, E0i, e0stride,
                             fast ? out + EY_ELEMS : nullptr);

    if (!fast) {
        long long cnt; int mode;
        if      (out_size == EY_ELEMS + 2 * NN) { mode = 1; cnt = out_size; }
        else if (out_size == EY_ELEMS)          { mode = 2; cnt = out_size; }
        else if (out_size == 2 * NN)            { mode = 3; cnt = out_size; }
        else if (out_size == NN)                { mode = 4; cnt = out_size; }
        else { mode = 5; cnt = out_size / 4; }
        if (cnt < 1) cnt = 1;
        pack_kernel<<<(unsigned)((cnt + 255) / 256), 256>>>(out, cnt, mode);
    }
}

// round 16
// speedup vs baseline: 1.2401x; 1.2306x over previous
#include <cuda_runtime.h>
#include <cuda_bf16.h>
#include <cstdint>

// ---------------- problem constants ----------------
#define NN       2304
#define KDIM     128
#define KP       64              // packed bf16-pair count along K
#define NCOLS    14400
#define E0W      1060
#define EY_ELEMS (NN * NCOLS)    // 33177600
#define E0_ELEMS 1123600

// GEMM tiling (round-13 champion shape)
#define GM 256                   // rows per CTA (2 row-tiles of 16 per warp)
#define GN 64                    // cols per CTA (8 column tiles of 8)
#define NMG (NN / 16)            // 144 row fragment groups
#define FRAG_N (NMG * 8 * 32)    // A fragments per plane = 36864
#define NCT (NCOLS / 8)          // 1800 column tiles
#define FRAGB_N (NCT * 8 * 32)   // B fragments = 460800

// ---------------- scratch (device globals, allocation-free) ----------------
__device__ float    g_eta[NN];
__device__ uint32_t g_hhi[NN * KP];
__device__ uint32_t g_hlo[NN * KP];
__device__ __align__(16) uint4 g_fragHi[FRAG_N];   // A fragments (hi plane)
__device__ __align__(16) uint4 g_fragLo[FRAG_N];   // A fragments (lo plane)
__device__ __align__(16) uint2 g_BfragH[FRAGB_N];  // B fragments hi (bh0,bh1)
__device__ __align__(16) uint2 g_BfragL[FRAGB_N];  // B fragments lo (bl0,bl1)
__device__ __align__(16) int g_tbl[NCOLS];         // packed (tij<<9 | ab)
__device__ __align__(16) float g_Ey[EY_ELEMS];     // fallback output modes only
__device__ float    g_Tre[NN];
__device__ float    g_Tim[NN];
__device__ float    g_zero[2 * E0_ELEMS];          // universal null fallback

// ---------------------------------------------------------------------------
// helpers
// ---------------------------------------------------------------------------
__device__ __forceinline__ void bf16_split_pack(float x0, float x1,
                                                uint32_t& hi, uint32_t& lo)
{
    __nv_bfloat16 h0 = __float2bfloat16_rn(x0);
    __nv_bfloat16 h1 = __float2bfloat16_rn(x1);
    hi = (uint32_t)__bfloat16_as_ushort(h0)
       | ((uint32_t)__bfloat16_as_ushort(h1) << 16);
    __nv_bfloat16 l0 = __float2bfloat16_rn(x0 - __bfloat162float(h0));
    __nv_bfloat16 l1 = __float2bfloat16_rn(x1 - __bfloat162float(h1));
    lo = (uint32_t)__bfloat16_as_ushort(l0)
       | ((uint32_t)__bfloat16_as_ushort(l1) << 16);
}

// D += A(16x16 bf16) * B(16x8 bf16), fp32 accum. sm_80+ HMMA.
__device__ __forceinline__ void mma_bf16(float* c, const uint4& a,
                                         uint32_t b0, uint32_t b1)
{
    asm volatile(
        "mma.sync.aligned.m16n8k16.row.col.f32.bf16.bf16.f32 "
        "{%0,%1,%2,%3}, {%4,%5,%6,%7}, {%8,%9}, {%0,%1,%2,%3};\n"
        : "+f"(c[0]), "+f"(c[1]), "+f"(c[2]), "+f"(c[3])
        : "r"(a.x), "r"(a.y), "r"(a.z), "r"(a.w), "r"(b0), "r"(b1));
}

// ---------------------------------------------------------------------------
// Kernel 1: the two small MLPs; also emits split-bf16 packed h.
// ---------------------------------------------------------------------------
__global__ void __launch_bounds__(128) mlp_kernel(
    const float* hs,
    const float* nW0, const float* nb0, const float* nW1, const float* nb1,
    const float* nW2, const float* nb2,
    const float* eW0, const float* eb0, const float* eW1, const float* eb1)
{
    const float* HS  = hs  ? hs  : g_zero;
    const float* NW0 = nW0 ? nW0 : g_zero;  const float* NB0 = nb0 ? nb0 : g_zero;
    const float* NW1 = nW1 ? nW1 : g_zero;  const float* NB1 = nb1 ? nb1 : g_zero;
    const float* NW2 = nW2 ? nW2 : g_zero;  const float* NB2 = nb2 ? nb2 : g_zero;
    const float* EW0 = eW0 ? eW0 : g_zero;  const float* EB0 = eb0 ? eb0 : g_zero;
    const float* EW1 = eW1 ? eW1 : g_zero;  const float* EB1 = eb1 ? eb1 : g_zero;

    int p = blockIdx.x, j = threadIdx.x;
    float x = HS[p];
    __shared__ float s1[KDIM], s2[KDIM];

    // ---- neff branch ----
    s1[j] = fmaxf(fmaf(x, NW0[j], NB0[j]), 0.0f);
    __syncthreads();
    float acc = NB1[j];
#pragma unroll 8
    for (int k = 0; k < KDIM; ++k) acc = fmaf(s1[k], NW1[k * KDIM + j], acc);
    float h2 = fmaxf(acc, 0.0f);
    __syncthreads();
    s2[j] = h2 * NW2[j];
    __syncthreads();
    for (int off = 64; off > 0; off >>= 1) {
        if (j < off) s2[j] += s2[j + off];
        __syncthreads();
    }
    if (j == 0) {
        float neff = s2[0] + NB2[0];
        g_eta[p] = neff / (neff + 1.0f);   // N0 = 1
    }
    __syncthreads();

    // ---- enn branch ----
    s1[j] = fmaxf(fmaf(x, EW0[j], EB0[j]), 0.0f);
    __syncthreads();
    acc = EB1[j];
#pragma unroll 8
    for (int k = 0; k < KDIM; ++k) acc = fmaf(s1[k], EW1[k * KDIM + j], acc);
    float hval = fmaxf(acc, 0.0f);
    __syncthreads();
    s2[j] = hval;
    __syncthreads();
    if (j < KP) {
        uint32_t hi, lo;
        bf16_split_pack(s2[2 * j], s2[2 * j + 1], hi, lo);
        g_hhi[p * KP + j] = hi;
        g_hlo[p * KP + j] = lo;
    }
}

// ---------------------------------------------------------------------------
// Kernel 1b: pack eW2 into B-FRAGMENT order, hi/lo planes (+ esum table).
// Values bit-identical to rounds 6-15 (same kp0/kp1/col mapping).
// ---------------------------------------------------------------------------
__global__ void __launch_bounds__(256) wfrag_kernel(const float* W_in)
{
    const float* W = W_in ? W_in : g_zero;
    int id = blockIdx.x * 256 + threadIdx.x;          // over FRAGB_N

    // piggyback: esum gather table (first NCOLS threads)
    if (id < NCOLS) {
        int e = id;
        int y = e / 120, x = e - y * 120;
        int i = y / 20, a = y - i * 20;
        int j = x / 20, b = x - j * 20;
        int tij = (i * 20) * E0W + j * 20;
        g_tbl[e] = (tij << 9) | (a * 20 + b);
    }

    if (id >= FRAGB_N) return;
    int lane = id & 31;
    int ks   = (id >> 5) & 7;
    int ct   = id >> 8;
    int qrow = lane >> 2, qk = lane & 3;
    int col  = ct * 8 + qrow;
    int kp0  = ks * 8 + qk;      // b0: k-pairs kb+qk
    int kp1  = kp0 + 4;          // b1: k-pairs kb+qk+4

    float x0 = W[(2 * kp0)     * NCOLS + col];
    float x1 = W[(2 * kp0 + 1) * NCOLS + col];
    float y0 = W[(2 * kp1)     * NCOLS + col];
    float y1 = W[(2 * kp1 + 1) * NCOLS + col];

    uint2 vh, vl;
    bf16_split_pack(x0, x1, vh.x, vl.x);   // bh0, bl0
    bf16_split_pack(y0, y1, vh.y, vl.y);   // bh1, bl1
    g_BfragH[id] = vh;
    g_BfragL[id] = vl;
}

// ---------------------------------------------------------------------------
// Kernel 1c: swizzle h into A-fragment order (round-8 proven grid-stride).
// ---------------------------------------------------------------------------
__global__ void __launch_bounds__(256) hfrag_kernel()
{
    int id = blockIdx.x * 256 + threadIdx.x;
    if (id >= 2 * FRAG_N) return;
    int plane = id / FRAG_N;
    int r = id - plane * FRAG_N;
    int lane = r & 31;
    int ks = (r >> 5) & 7;
    int mg = r >> 8;
    int qrow = lane >> 2, qk = lane & 3;
    int row = mg * 16 + qrow;
    int kp  = ks * 8 + qk;
    const uint32_t* src = plane ? g_hlo : g_hhi;
    uint4 v;
    v.x = src[row * KP + kp];
    v.y = src[(row + 8) * KP + kp];
    v.z = src[row * KP + kp + 4];
    v.w = src[(row + 8) * KP + kp + 4];
    (plane ? g_fragLo : g_fragHi)[r] = v;
}

// ---------------------------------------------------------------------------
// Kernel 2: HMMA bf16 split GEMM. Round-13 shape (GM=256, smem B tile, 18x
// reuse, 2 CTA/SM) with fragment-format smem in TWO planes: inner loop does
// 2x LDS.64 per (s,ks) — half of round-13's LDS count, same 4-reg b footprint
// as round 13 (vs round 15's uint4 that blew regs to 140 / 1 CTA).
// Accumulation order per output identical to rounds 8/13.
// ---------------------------------------------------------------------------
__global__ void __launch_bounds__(256, 2) gemm_mma(
    const float* bias_in, float* eyout)
{
    const float* bias = bias_in ? bias_in : g_zero;
    float* o = eyout ? eyout : g_Ey;

    __shared__ __align__(16) uint2 sBh[2048];   // 8 ct x 8 ks x 32 lanes, 16KB
    __shared__ __align__(16) uint2 sBl[2048];   // 16KB

    const int c0  = blockIdx.x * GN;
    const int ct0 = blockIdx.x * 8;
    const int p0  = blockIdx.y * GM;
    const int t = threadIdx.x;
    const int w = t >> 5, lane = t & 31;

    // stage B fragments: pure contiguous copies (fully coalesced)
    {
        const uint2* srcH = g_BfragH + ct0 * 256;
        const uint2* srcL = g_BfragL + ct0 * 256;
#pragma unroll
        for (int i = 0; i < 8; ++i) {
            sBh[i * 256 + t] = srcH[i * 256 + t];
            sBl[i * 256 + t] = srcL[i * 256 + t];
        }
    }
    __syncthreads();

    const int r0   = p0 + w * 32;
    const int qrow = lane >> 2;
    const int qk   = lane & 3;
    const int mg0  = r0 >> 4;

    float acc[2][8][4];
#pragma unroll
    for (int u = 0; u < 2; ++u)
#pragma unroll
        for (int s = 0; s < 8; ++s)
#pragma unroll
            for (int q = 0; q < 4; ++q) acc[u][s][q] = 0.0f;

    for (int ks = 0; ks < 8; ++ks) {
        uint4 ah0 = g_fragHi[(mg0 * 8 + ks) * 32 + lane];
        uint4 al0 = g_fragLo[(mg0 * 8 + ks) * 32 + lane];
        uint4 ah1 = g_fragHi[((mg0 + 1) * 8 + ks) * 32 + lane];
        uint4 al1 = g_fragLo[((mg0 + 1) * 8 + ks) * 32 + lane];

#pragma unroll
        for (int s = 0; s < 8; ++s) {
            uint2 bh = sBh[(s * 8 + ks) * 32 + lane];   // LDS.64
            uint2 bl = sBl[(s * 8 + ks) * 32 + lane];   // LDS.64
            mma_bf16(acc[0][s], ah0, bh.x, bh.y);   // hi·hi
            mma_bf16(acc[0][s], ah0, bl.x, bl.y);   // hi·lo
            mma_bf16(acc[0][s], al0, bh.x, bh.y);   // lo·hi
            mma_bf16(acc[1][s], ah1, bh.x, bh.y);
            mma_bf16(acc[1][s], ah1, bl.x, bl.y);
            mma_bf16(acc[1][s], al1, bh.x, bh.y);
        }
    }

    // epilogue: bias + direct coalesced float2 stores (two row tiles)
#pragma unroll
    for (int s = 0; s < 8; ++s) {
        int c = c0 + s * 8 + qk * 2;
        float b0 = bias[c], b1 = bias[c + 1];
#pragma unroll
        for (int u = 0; u < 2; ++u) {
            size_t r = (size_t)(r0 + 16 * u + qrow);
            float2 v0 = make_float2(acc[u][s][0] + b0, acc[u][s][1] + b1);
            float2 v1 = make_float2(acc[u][s][2] + b0, acc[u][s][3] + b1);
            *(float2*)&o[r * NCOLS + c]       = v0;
            *(float2*)&o[(r + 8) * NCOLS + c] = v1;
        }
    }
}

// ---------------------------------------------------------------------------
// Kernel 3: T[p] = 0.005 * eta[p] * sum_e Ey[p,e] * E0_slice[p,e]
// float4 Ey + int4 table, separate E0r/E0i gathers (round-13 proven).
// ---------------------------------------------------------------------------
__global__ void __launch_bounds__(256) esum_kernel(
    const float* ey_in, const float* E0r_in, const float* E0i_in,
    int stride, float* outT)
{
    const float* ey  = ey_in  ? ey_in  : g_Ey;
    const float* E0r = E0r_in ? E0r_in : g_zero;
    const float* E0i = E0i_in ? E0i_in : g_zero;

    const int p = blockIdx.x, t = threadIdx.x;
    const int f0  = p * 400;
    const int r0p = f0 / 960;
    const int c0p = f0 - r0p * 960;
    const int base = r0p * E0W + c0p;
    const int lim  = 960 - c0p;

    float sre = 0.f, sim = 0.f;
    const float4* ey4  = (const float4*)(ey + (size_t)p * NCOLS);
    const int4*   tbl4 = (const int4*)g_tbl;

    for (int q = t; q < NCOLS / 4; q += 256) {
        int4   tb = tbl4[q];
        float4 g  = ey4[q];

        int ab0 = tb.x & 511;
        int i0  = base + (tb.x >> 9) + ab0 + ((ab0 >= lim) ? 100 : 0);
        int ab1 = tb.y & 511;
        int i1  = base + (tb.y >> 9) + ab1 + ((ab1 >= lim) ? 100 : 0);
        int ab2 = tb.z & 511;
        int i2  = base + (tb.z >> 9) + ab2 + ((ab2 >= lim) ? 100 : 0);
        int ab3 = tb.w & 511;
        int i3  = base + (tb.w >> 9) + ab3 + ((ab3 >= lim) ? 100 : 0);

        sre = fmaf(g.x, E0r[i0 * stride], sre);
        sim = fmaf(g.x, E0i[i0 * stride], sim);
        sre = fmaf(g.y, E0r[i1 * stride], sre);
        sim = fmaf(g.y, E0i[i1 * stride], sim);
        sre = fmaf(g.z, E0r[i2 * stride], sre);
        sim = fmaf(g.z, E0i[i2 * stride], sim);
        sre = fmaf(g.w, E0r[i3 * stride], sre);
        sim = fmaf(g.w, E0i[i3 * stride], sim);
    }

#pragma unroll
    for (int off = 16; off > 0; off >>= 1) {
        sre += __shfl_down_sync(0xffffffffu, sre, off);
        sim += __shfl_down_sync(0xffffffffu, sim, off);
    }
    __shared__ float wr[8], wi[8];
    if ((t & 31) == 0) { wr[t >> 5] = sre; wi[t >> 5] = sim; }
    __syncthreads();
    if (t == 0) {
        float tre = 0.f, tim = 0.f;
        for (int q = 0; q < 8; ++q) { tre += wr[q]; tim += wi[q]; }
        float s = 0.005f * g_eta[p];
        g_Tre[p] = s * tre;
        g_Tim[p] = s * tim;
        if (outT) outT[p] = s * tre;
    }
}

// ---------------------------------------------------------------------------
// Kernel 4 (fallback modes only): scalar-float pack, never exceeds cnt.
// ---------------------------------------------------------------------------
__global__ void pack_kernel(float* out, long long cnt, int mode)
{
    long long i = (long long)blockIdx.x * 256 + threadIdx.x;
    if (i >= cnt) return;
    float v = 0.f;
    if (mode == 1 || mode == 5) {
        if (i < EY_ELEMS) v = g_Ey[i];
        else {
            long long q = i - EY_ELEMS;
            if (q < 2 * NN) v = (q & 1) ? g_Tim[q >> 1] : g_Tre[q >> 1];
        }
    } else if (mode == 2) v = g_Ey[i];
    else if (mode == 3) v = (i & 1) ? g_Tim[i >> 1] : g_Tre[i >> 1];
    else if (mode == 4) v = g_Tre[i];
    out[i] = v;
}

// ---------------------------------------------------------------------------
extern "C" void kernel_launch(void* const* d_in, const int* in_sizes, int n_in,
                              void* d_out, int out_size)
{
    if (n_in > 64) n_in = 64;
    bool used[64];
    for (int i = 0; i < 64; ++i) used[i] = false;
    auto take = [&](int sz) -> const float* {
        for (int i = 0; i < n_in; ++i)
            if (!used[i] && in_sizes[i] == sz) {
                used[i] = true;
                return (const float*)d_in[i];
            }
        return nullptr;
    };

    const float* hs = take(2304);
    const float* E0r; const float* E0i; int e0stride;
    {
        const float* a = take(E0_ELEMS);
        if (a) { E0r = a; E0i = take(E0_ELEMS); e0stride = 1; }
        else {
            const float* c1 = take(2 * E0_ELEMS);
            const float* c2 = take(2 * E0_ELEMS);
            if (c1 && c2)      { E0r = c1; E0i = c2;     e0stride = 2; }
            else if (c1)       { E0r = c1; E0i = c1 + 1; e0stride = 2; }
            else               { E0r = nullptr; E0i = nullptr; e0stride = 1; }
        }
    }
    const float* nW0 = take(128);
    const float* nb0 = take(128);
    const float* nW1 = take(16384);
    const float* nb1 = take(128);
    const float* nW2 = take(128);
    const float* nb2 = take(1);
    const float* eW0 = take(128);
    const float* eb0 = take(128);
    const float* eW1 = take(16384);
    const float* eb1 = take(128);
    const float* eW2 = take(1843200);
    const float* eb2 = take(14400);
    float* out = (float*)d_out;

    const bool fast = (out_size == EY_ELEMS + NN);

    mlp_kernel<<<NN, 128>>>(hs, nW0, nb0, nW1, nb1, nW2, nb2,
                            eW0, eb0, eW1, eb1);
    wfrag_kernel<<<(FRAGB_N + 255) / 256, 256>>>(eW2);  // + esum table
    hfrag_kernel<<<(2 * FRAG_N + 255) / 256, 256>>>();

    gemm_mma<<<dim3(NCOLS / GN, NN / GM), 256>>>(eb2, fast ? out : nullptr);

    esum_kernel<<<NN, 256>>>(fast ? out : nullptr, E0r, E0i, e0stride,
                             fast ? out + EY_ELEMS : nullptr);

    if (!fast) {
        long long cnt; int mode;
        if      (out_size == EY_ELEMS + 2 * NN) { mode = 1; cnt = out_size; }
        else if (out_size == EY_ELEMS)          { mode = 2; cnt = out_size; }
        else if (out_size == 2 * NN)            { mode = 3; cnt = out_size; }
        else if (out_size == NN)                { mode = 4; cnt = out_size; }
        else { mode = 5; cnt = out_size / 4; }
        if (cnt < 1) cnt = 1;
        pack_kernel<<<(unsigned)((cnt + 255) / 256), 256>>>(out, cnt, mode);
    }
}